// round 16
// baseline (speedup 1.0000x reference)
#include <cuda_runtime.h>
#include <cuda_fp16.h>
#include <math.h>
#include <stdint.h>

// ---------------------------------------------------------------------------
// Problem constants
// ---------------------------------------------------------------------------
#define D_IN   64
#define HID    256
#define NPAR   800
#define MINW   0.001f
#define MIND   0.001f
#define EPSC   1e-12f

// Prepared weights: W1 fp16 hi/lo split (phase-1 3-term);
// W2 fp16 fragment-ordered for direct LDG into mma B-operands.
__device__ __half g_W1h[HID * 32], g_W1l[HID * 32];
__device__ uint2  g_W2p[100 * 16 * 32];

// ---------------------------------------------------------------------------
// smem layout (bytes) — 64 rows/CTA, 94976 B total -> 2 CTAs per SM
// stage: [row][ch 0..7][28 floats]  (row stride 224 f = 896 B, ch stride 112 B)
// ---------------------------------------------------------------------------
#define OFF_AH   0                    // A (H) fp16 : 64 rows x 512B (swizzled)
#define OFF_U    32768                // union: phase1 staging (40K) / stage (57344)
#define OFF_B2P  90112                // padded b2: 32 ch x 28 f = 3584 B
#define OFF_B1   93696                // 256 f
#define OFF_LAD  94720                // 64 f
#define SMEM_TOT 94976

// ---------------------------------------------------------------------------
// helpers
// ---------------------------------------------------------------------------
__device__ __forceinline__ uint32_t smem_u32(const void* p) {
    uint32_t a;
    asm("{ .reg .u64 t; cvta.to.shared.u64 t, %1; cvt.u32.u64 %0, t; }" : "=r"(a) : "l"(p));
    return a;
}
__device__ __forceinline__ void ldsm4(uint32_t r[4], uint32_t addr) {
    asm volatile("ldmatrix.sync.aligned.m8n8.x4.shared.b16 {%0,%1,%2,%3}, [%4];"
                 : "=r"(r[0]), "=r"(r[1]), "=r"(r[2]), "=r"(r[3]) : "r"(addr));
}
__device__ __forceinline__ void mma16816(float c[4], const uint32_t a[4], const uint32_t b[2]) {
    asm volatile("mma.sync.aligned.m16n8k16.row.col.f32.f16.f16.f32 "
                 "{%0,%1,%2,%3}, {%4,%5,%6,%7}, {%8,%9}, {%0,%1,%2,%3};"
                 : "+f"(c[0]), "+f"(c[1]), "+f"(c[2]), "+f"(c[3])
                 : "r"(a[0]), "r"(a[1]), "r"(a[2]), "r"(a[3]), "r"(b[0]), "r"(b[1]));
}
__device__ __forceinline__ uint32_t packh2(float v0, float v1) {
    __half h0 = __float2half_rn(v0), h1 = __float2half_rn(v1);
    return (uint32_t)__half_as_ushort(h0) | ((uint32_t)__half_as_ushort(h1) << 16);
}

// A region (512B rows): byte = r*512 + ((g ^ (r&7))<<4); g = 16B group 0..31
__device__ __forceinline__ uint32_t aoff(int r, int g) {
    return (uint32_t)(r * 512 + ((g ^ (r & 7)) << 4));
}
// 64B-row regions (X, W1t): byte = n*64 + ((g ^ ((n>>1)&3))<<4); g 0..3
__device__ __forceinline__ uint32_t boff(int n, int g) {
    return (uint32_t)(n * 64 + ((g ^ ((n >> 1) & 3)) << 4));
}

// ---------------------------------------------------------------------------
// prep (256-thread blocks): blocks 0..199 pack W2 fragments; 200..231 split W1
// ---------------------------------------------------------------------------
__global__ void kprep(const float* __restrict__ W1, const float* __restrict__ W2) {
    int gi = blockIdx.x * 256 + threadIdx.x;
    if (blockIdx.x < 200) {
        int b = gi >> 5, l = gi & 31;
        int J = b >> 4, q = b & 15;
        int n  = J * 8 + (l >> 2);
        int k0 = q * 16 + (l & 3) * 2;
        uint32_t w0 = packh2(W2[(size_t)k0 * NPAR + n],       W2[(size_t)(k0 + 1) * NPAR + n]);
        uint32_t w1 = packh2(W2[(size_t)(k0 + 8) * NPAR + n], W2[(size_t)(k0 + 9) * NPAR + n]);
        g_W2p[(size_t)b * 32 + l] = make_uint2(w0, w1);
    } else {
        int e = gi - 200 * 256;
        int nn = e >> 5, l = e & 31;
        float v = W1[l * HID + nn];
        __half h = __float2half_rn(v);
        g_W1h[nn * 32 + l] = h;
        g_W1l[nn * 32 + l] = __float2half_rn(v - __half2float(h));
    }
}

// ---------------------------------------------------------------------------
// fused kernel: 256 threads, 64 rows per CTA, 2 CTAs/SM
// ---------------------------------------------------------------------------
__global__ __launch_bounds__(256, 2)
void kmain(const float* __restrict__ X,
           const float* __restrict__ b1,
           const float* __restrict__ b2,
           float* __restrict__ out, int B)
{
    extern __shared__ char sm[];
    const uint32_t sb = smem_u32(sm);
    const int tid = threadIdx.x, lane = tid & 31, wid = tid >> 5;
    const int wm = wid >> 2, wn = wid & 3;     // wm 0..1 (m32 each), wn 0..3
    const int rbase = blockIdx.x * 64;

    float* b1s   = (float*)(sm + OFF_B1);
    float* b2p   = (float*)(sm + OFF_B2P);
    float* lad   = (float*)(sm + OFF_LAD);
    float* stage = (float*)(sm + OFF_U);

    // ---- init ----
    b1s[tid] = b1[tid];
    for (int i = tid; i < NPAR; i += 256) {          // pad b2 to 28 f/channel
        int ch = i / 25, o = i - ch * 25;
        b2p[ch * 28 + o] = b2[i];
    }
    if (tid < 64) lad[tid] = 0.f;
    for (int i = tid; i < 512; i += 256) {          // identity copy (64 rows x 8 f4)
        int r = i >> 3, q = i & 7;
        ((float4*)(out + (size_t)(rbase + r) * D_IN))[q] =
            ((const float4*)(X + (size_t)(rbase + r) * D_IN))[q];
    }

    // ---- phase-1 operand staging: X split + W1t ----
    {
        int r = tid >> 2, q = tid & 3;               // 64 rows x 4 groups
        const float* xp = X + (size_t)(rbase + r) * D_IN + q * 8;
        float4 v0 = *(const float4*)xp, v1 = *(const float4*)(xp + 4);
        float vv[8] = {v0.x, v0.y, v0.z, v0.w, v1.x, v1.y, v1.z, v1.w};
        ushort hh[8], hl[8];
#pragma unroll
        for (int j = 0; j < 8; j++) {
            __half h = __float2half_rn(vv[j]);
            hh[j] = __half_as_ushort(h);
            hl[j] = __half_as_ushort(__float2half_rn(vv[j] - __half2float(h)));
        }
        uint32_t off = boff(r, q);
        *(uint4*)(sm + OFF_U + off)        = *(uint4*)hh;   // XH (4KB)
        *(uint4*)(sm + OFF_U + 4096 + off) = *(uint4*)hl;   // XL (4KB)
    }
#pragma unroll
    for (int s = 0; s < 8; s++) {
        int i = tid + s * 256;          // 2048 = 2 splits x 256 rows x 4 groups
        int split = i >> 10, ii = i & 1023;
        int n = ii >> 2, g = ii & 3;
        const __half* src = split ? g_W1l : g_W1h;
        uint4 v = *(const uint4*)(src + n * 32 + g * 8);
        *(uint4*)(sm + OFF_U + 8192 + split * 16384 + boff(n, g)) = v;
    }
    __syncthreads();

    // ---- phase-1 mma: H = relu(X @ W1 + b1), 3-term, warp tile m32 x n64 ----
    float acc1[2][8][4];
#pragma unroll
    for (int i = 0; i < 2; i++)
#pragma unroll
        for (int j = 0; j < 8; j++)
#pragma unroll
            for (int c = 0; c < 4; c++) acc1[i][j][c] = 0.f;

#pragma unroll
    for (int t = 0; t < 2; t++) {
        uint32_t aH[2][4], aL[2][4], bb[8][2];
#pragma unroll
        for (int i = 0; i < 2; i++) {
            int r = wm * 32 + i * 16 + (lane & 15);
            int g = 2 * t + (lane >> 4);
            ldsm4(aH[i], sb + OFF_U + boff(r, g));          // XH
            ldsm4(aL[i], sb + OFF_U + 4096 + boff(r, g));   // XL
        }
#pragma unroll
        for (int p = 0; p < 4; p++) {
            int jj = wn * 8 + ((lane < 16) ? 2 * p : 2 * p + 1);
            int n = jj * 8 + (lane & 7);
            int g = 2 * t + ((lane >> 3) & 1);
            uint32_t r4[4];
            ldsm4(r4, sb + OFF_U + 8192 + boff(n, g));      // W1H
            bb[2 * p][0] = r4[0]; bb[2 * p][1] = r4[1];
            bb[2 * p + 1][0] = r4[2]; bb[2 * p + 1][1] = r4[3];
        }
#pragma unroll
        for (int i = 0; i < 2; i++)
#pragma unroll
            for (int j = 0; j < 8; j++) {
                mma16816(acc1[i][j], aH[i], bb[j]);
                mma16816(acc1[i][j], aL[i], bb[j]);
            }
#pragma unroll
        for (int p = 0; p < 4; p++) {
            int jj = wn * 8 + ((lane < 16) ? 2 * p : 2 * p + 1);
            int n = jj * 8 + (lane & 7);
            int g = 2 * t + ((lane >> 3) & 1);
            uint32_t r4[4];
            ldsm4(r4, sb + OFF_U + 24576 + boff(n, g));     // W1L
            bb[2 * p][0] = r4[0]; bb[2 * p][1] = r4[1];
            bb[2 * p + 1][0] = r4[2]; bb[2 * p + 1][1] = r4[3];
        }
#pragma unroll
        for (int i = 0; i < 2; i++)
#pragma unroll
            for (int j = 0; j < 8; j++)
                mma16816(acc1[i][j], aH[i], bb[j]);
    }

    // ---- phase-1 epilogue: +b1, relu, single fp16 into A region ----
#pragma unroll
    for (int i = 0; i < 2; i++)
#pragma unroll
        for (int j = 0; j < 8; j++) {
            int col = wn * 64 + j * 8 + 2 * (lane & 3);
            float bv0 = b1s[col], bv1 = b1s[col + 1];
            int r0 = wm * 32 + i * 16 + (lane >> 2);
#pragma unroll
            for (int half = 0; half < 2; half++) {
                int r = r0 + half * 8;
                float v0 = fmaxf(acc1[i][j][2 * half] + bv0, 0.f);
                float v1 = fmaxf(acc1[i][j][2 * half + 1] + bv1, 0.f);
                uint32_t off = aoff(r, col >> 3) + (col & 7) * 2;
                *(uint32_t*)(sm + OFF_AH + off) = packh2(v0, v1);
            }
        }
    __syncthreads();

    // ---- phase-2: single-term GEMM, B-fragments via pipelined LDG ----
    uint2 Bq[2][7];
    {
        const uint2* bb0 = g_W2p + (size_t)wn * 512 + lane;   // nt = 0
#pragma unroll
        for (int t = 0; t < 7; t++)
            if (wn == 0 || t < 6) Bq[0][t] = bb0[t * 2048];
    }

    for (int nt = 0; nt < 4; nt++) {
        float acc[2][7][4];
#pragma unroll
        for (int i = 0; i < 2; i++)
#pragma unroll
            for (int t = 0; t < 7; t++)
#pragma unroll
                for (int c = 0; c < 4; c++) acc[i][t][c] = 0.f;

        const uint2* bbase = g_W2p + (size_t)(nt * 25 + wn) * 512 + lane;

#pragma unroll
        for (int q = 0; q < 16; q++) {
            const int cur = q & 1, nxt = cur ^ 1;
            if (q < 15) {
#pragma unroll
                for (int t = 0; t < 7; t++)
                    if (wn == 0 || t < 6) Bq[nxt][t] = bbase[t * 2048 + (q + 1) * 32];
            }
            uint32_t aH[2][4];
#pragma unroll
            for (int i = 0; i < 2; i++) {
                int r = wm * 32 + i * 16 + (lane & 15);
                int g = 2 * q + (lane >> 4);
                ldsm4(aH[i], sb + OFF_AH + aoff(r, g));
            }
#pragma unroll
            for (int t = 0; t < 7; t++)
                if (t < 6 || wn == 0) {
                    const uint32_t* bp = (const uint32_t*)&Bq[cur][t];
                    mma16816(acc[0][t], aH[0], bp);
                    mma16816(acc[1][t], aH[1], bp);
                }
        }

        // protect stage: previous nt's spline readers must be done (skip nt=0)
        if (nt) __syncthreads();

        // ---- stage all 64 rows into padded [row][ch][28] layout ----
#pragma unroll
        for (int i = 0; i < 2; i++)
#pragma unroll
            for (int t = 0; t < 7; t++)
                if (t < 6 || wn == 0) {
                    int col = (wn + 4 * t) * 8 + 2 * (lane & 3);
                    int c0 = col / 25,       o0 = col - c0 * 25;
                    int c1 = (col + 1) / 25, o1 = (col + 1) - c1 * 25;
                    int r0 = wm * 32 + i * 16 + (lane >> 2);
                    float* s0 = &stage[r0 * 224];
                    float* s1 = &stage[(r0 + 8) * 224];
                    s0[c0 * 28 + o0] = acc[i][t][0];
                    s0[c1 * 28 + o1] = acc[i][t][1];
                    s1[c0 * 28 + o0] = acc[i][t][2];
                    s1[c1 * 28 + o1] = acc[i][t][3];
                }
        __syncthreads();

        // ---- preload next nt's first B-fragments (LDG hides behind spline) ----
        if (nt < 3) {
            const uint2* bbn = g_W2p + (size_t)((nt + 1) * 25 + wn) * 512 + lane;
#pragma unroll
            for (int t = 0; t < 7; t++)
                if (wn == 0 || t < 6) Bq[0][t] = bbn[t * 2048];
        }

        // ---- spline: 64 rows x 8 channels, 2 channels per thread ----
        {
            const int rl = tid >> 2;            // 0..63
            const int grow = rbase + rl;
            const float* xrow = X + (size_t)grow * D_IN + 32;
            float ladsum = 0.f;
#pragma unroll
            for (int qq = 0; qq < 2; qq++) {
                const int lc = (tid & 3) + qq * 4;   // 0..7
                const int ch = nt * 8 + lc;
                const float4* sp4 = (const float4*)&stage[rl * 224 + lc * 28];
                const float4* bp4 = (const float4*)&b2p[ch * 28];
                float pr[28];
#pragma unroll
                for (int j = 0; j < 7; j++) {
                    float4 v = sp4[j], bv = bp4[j];
                    pr[4 * j + 0] = v.x + bv.x;
                    pr[4 * j + 1] = v.y + bv.y;
                    pr[4 * j + 2] = v.z + bv.z;
                    pr[4 * j + 3] = v.w + bv.w;
                }

                // widths: affine softmax; Σw == 1 analytically -> no renorm
                float mw = pr[0];
#pragma unroll
                for (int j = 1; j < 8; j++) mw = fmaxf(mw, pr[j]);
                float ew[8], sw = 0.f;
#pragma unroll
                for (int j = 0; j < 8; j++) { ew[j] = __expf(pr[j] - mw); sw += ew[j]; }
                float invw = __fdividef(1.f - MINW * 8.f, sw);
                float w[8], cw[9]; cw[0] = 0.f;
#pragma unroll
                for (int j = 0; j < 8; j++) {
                    w[j] = MINW + ew[j] * invw;
                    cw[j + 1] = cw[j] + w[j];
                }

                // heights: same
                float mhh = pr[8];
#pragma unroll
                for (int j = 1; j < 8; j++) mhh = fmaxf(mhh, pr[8 + j]);
                float eh[8], sh = 0.f;
#pragma unroll
                for (int j = 0; j < 8; j++) { eh[j] = __expf(pr[8 + j] - mhh); sh += eh[j]; }
                float invh = __fdividef(1.f - MINW * 8.f, sh);
                float hh[8], chh[9]; chh[0] = 0.f;
#pragma unroll
                for (int j = 0; j < 8; j++) {
                    hh[j] = MINW + eh[j] * invh;
                    chh[j + 1] = chh[j] + hh[j];
                }

                const float x = xrow[ch];
                const bool inside = (x >= -10.f) && (x <= 10.f);
                float xs = fminf(fmaxf((x + 10.f) * 0.05f, 0.f), 1.f);

                // bin selection first (raw u values selected too)
                float xk = cw[0], wk = w[0], yk = chh[0], hk = hh[0];
                float u0 = pr[16], u1 = pr[17];
#pragma unroll
                for (int i = 1; i < 8; i++) {
                    if (xs >= cw[i]) {
                        xk = cw[i]; wk = w[i]; yk = chh[i]; hk = hh[i];
                        u0 = pr[16 + i]; u1 = pr[17 + i];
                    }
                }
                // lazy softplus on the two selected knots
                float dk  = MIND + fmaxf(u0, 0.f) + __logf(1.f + __expf(-fabsf(u0)));
                float dk1 = MIND + fmaxf(u1, 0.f) + __logf(1.f + __expf(-fabsf(u1)));

                float invwk = __fdividef(1.f, wk + EPSC);     // shared rcp
                float t   = fminf(fmaxf((xs - xk) * invwk, 0.f), 1.f);
                float a   = (hk + EPSC) * invwk;
                float omt = 1.f - t;
                float num = a * t * t + dk * t * omt;
                float den = a + (dk + dk1 - 2.f * a) * t * omt;
                float s   = __fdividef(num, den + EPSC);
                float y   = (yk + hk * s) * 20.f - 10.f;
                float dnum = a * a * (dk1 * t * t + 2.f * a * t * omt + dk * omt * omt);
                float dydx = __fdividef(dnum, den * den + EPSC);
                float ladv = __logf(fmaxf(dydx, 1e-12f));

                out[(size_t)grow * D_IN + 32 + ch] = inside ? y : x;
                ladsum += inside ? ladv : 0.f;
            }
            // reduce 4 lanes (8 channels) per row
            ladsum += __shfl_xor_sync(0xffffffffu, ladsum, 1);
            ladsum += __shfl_xor_sync(0xffffffffu, ladsum, 2);
            if ((lane & 3) == 0) lad[rl] += ladsum;
        }
    }

    __syncthreads();
    if (tid < 64) out[(size_t)B * D_IN + rbase + tid] = lad[tid];
}

// ---------------------------------------------------------------------------
extern "C" void kernel_launch(void* const* d_in, const int* in_sizes, int n_in,
                              void* d_out, int out_size)
{
    const float* X  = (const float*)d_in[0];
    const float* W1 = (const float*)d_in[1];
    const float* b1 = (const float*)d_in[2];
    const float* W2 = (const float*)d_in[3];
    const float* b2 = (const float*)d_in[4];
    float* out = (float*)d_out;

    const int B = in_sizes[0] / D_IN;

    cudaFuncSetAttribute(kmain, cudaFuncAttributeMaxDynamicSharedMemorySize, SMEM_TOT);

    kprep<<<232, 256>>>(W1, W2);
    kmain<<<B / 64, 256, SMEM_TOT>>>(X, b1, b2, out, B);
}

// round 17
// speedup vs baseline: 1.3597x; 1.3597x over previous
#include <cuda_runtime.h>
#include <cuda_fp16.h>
#include <math.h>
#include <stdint.h>

// ---------------------------------------------------------------------------
// Problem constants
// ---------------------------------------------------------------------------
#define D_IN   64
#define HID    256
#define NPAR   800
#define MINW   0.001f
#define MIND   0.001f
#define EPSC   1e-12f

// Prepared weights: W1 fp16 hi/lo split (phase-1 3-term);
// W2 fp16 fragment-ordered for direct LDG into mma B-operands.
__device__ __half g_W1h[HID * 32], g_W1l[HID * 32];
__device__ uint2  g_W2p[100 * 16 * 32];

// ---------------------------------------------------------------------------
// smem layout (bytes) — 64 rows/CTA, 90112 B total -> 2 CTAs per SM
// ---------------------------------------------------------------------------
#define SSTR     204                  // stage row stride in floats (R15 layout)
#define OFF_AH   0                    // A (H) fp16 : 64 rows x 512B (swizzled)
#define OFF_U    32768                // union: phase1 staging (40K) / stage (52224)
#define OFF_B2P  84992                // padded b2: 32 ch x 28 f = 3584 B
#define OFF_B1   88576                // 256 f
#define OFF_LAD  89600                // 64 f
#define SMEM_TOT 89856

// ---------------------------------------------------------------------------
// helpers
// ---------------------------------------------------------------------------
__device__ __forceinline__ uint32_t smem_u32(const void* p) {
    uint32_t a;
    asm("{ .reg .u64 t; cvta.to.shared.u64 t, %1; cvt.u32.u64 %0, t; }" : "=r"(a) : "l"(p));
    return a;
}
__device__ __forceinline__ void ldsm4(uint32_t r[4], uint32_t addr) {
    asm volatile("ldmatrix.sync.aligned.m8n8.x4.shared.b16 {%0,%1,%2,%3}, [%4];"
                 : "=r"(r[0]), "=r"(r[1]), "=r"(r[2]), "=r"(r[3]) : "r"(addr));
}
__device__ __forceinline__ void mma16816(float c[4], const uint32_t a[4], const uint32_t b[2]) {
    asm volatile("mma.sync.aligned.m16n8k16.row.col.f32.f16.f16.f32 "
                 "{%0,%1,%2,%3}, {%4,%5,%6,%7}, {%8,%9}, {%0,%1,%2,%3};"
                 : "+f"(c[0]), "+f"(c[1]), "+f"(c[2]), "+f"(c[3])
                 : "r"(a[0]), "r"(a[1]), "r"(a[2]), "r"(a[3]), "r"(b[0]), "r"(b[1]));
}
__device__ __forceinline__ uint32_t packh2(float v0, float v1) {
    __half h0 = __float2half_rn(v0), h1 = __float2half_rn(v1);
    return (uint32_t)__half_as_ushort(h0) | ((uint32_t)__half_as_ushort(h1) << 16);
}

// A region (512B rows): byte = r*512 + ((g ^ (r&7))<<4); g = 16B group 0..31
__device__ __forceinline__ uint32_t aoff(int r, int g) {
    return (uint32_t)(r * 512 + ((g ^ (r & 7)) << 4));
}
// 64B-row regions (X, W1t): byte = n*64 + ((g ^ ((n>>1)&3))<<4); g 0..3
__device__ __forceinline__ uint32_t boff(int n, int g) {
    return (uint32_t)(n * 64 + ((g ^ ((n >> 1) & 3)) << 4));
}

// ---------------------------------------------------------------------------
// prep (256-thread blocks): blocks 0..199 pack W2 fragments; 200..231 split W1
// ---------------------------------------------------------------------------
__global__ void kprep(const float* __restrict__ W1, const float* __restrict__ W2) {
    int gi = blockIdx.x * 256 + threadIdx.x;
    if (blockIdx.x < 200) {
        int b = gi >> 5, l = gi & 31;
        int J = b >> 4, q = b & 15;
        int n  = J * 8 + (l >> 2);
        int k0 = q * 16 + (l & 3) * 2;
        uint32_t w0 = packh2(W2[(size_t)k0 * NPAR + n],       W2[(size_t)(k0 + 1) * NPAR + n]);
        uint32_t w1 = packh2(W2[(size_t)(k0 + 8) * NPAR + n], W2[(size_t)(k0 + 9) * NPAR + n]);
        g_W2p[(size_t)b * 32 + l] = make_uint2(w0, w1);
    } else {
        int e = gi - 200 * 256;
        int nn = e >> 5, l = e & 31;
        float v = W1[l * HID + nn];
        __half h = __float2half_rn(v);
        g_W1h[nn * 32 + l] = h;
        g_W1l[nn * 32 + l] = __float2half_rn(v - __half2float(h));
    }
}

// ---------------------------------------------------------------------------
// fused kernel: 256 threads, 64 rows per CTA, 2 CTAs/SM
// ---------------------------------------------------------------------------
__global__ __launch_bounds__(256, 2)
void kmain(const float* __restrict__ X,
           const float* __restrict__ b1,
           const float* __restrict__ b2,
           float* __restrict__ out, int B)
{
    extern __shared__ char sm[];
    const uint32_t sb = smem_u32(sm);
    const int tid = threadIdx.x, lane = tid & 31, wid = tid >> 5;
    const int wm = wid >> 2, wn = wid & 3;     // wm 0..1 (m32 each), wn 0..3
    const int rbase = blockIdx.x * 64;

    float* b1s   = (float*)(sm + OFF_B1);
    float* b2p   = (float*)(sm + OFF_B2P);
    float* lad   = (float*)(sm + OFF_LAD);
    float* stage = (float*)(sm + OFF_U);

    // ---- init ----
    b1s[tid] = b1[tid];
    for (int i = tid; i < NPAR; i += 256) {          // pad b2 to 28 f/channel
        int ch = i / 25, o = i - ch * 25;
        b2p[ch * 28 + o] = b2[i];
    }
    if (tid < 64) lad[tid] = 0.f;
    for (int i = tid; i < 512; i += 256) {          // identity copy (64 rows x 8 f4)
        int r = i >> 3, q = i & 7;
        ((float4*)(out + (size_t)(rbase + r) * D_IN))[q] =
            ((const float4*)(X + (size_t)(rbase + r) * D_IN))[q];
    }

    // ---- phase-1 operand staging: X split + W1t ----
    {
        int r = tid >> 2, q = tid & 3;               // 64 rows x 4 groups
        const float* xp = X + (size_t)(rbase + r) * D_IN + q * 8;
        float4 v0 = *(const float4*)xp, v1 = *(const float4*)(xp + 4);
        float vv[8] = {v0.x, v0.y, v0.z, v0.w, v1.x, v1.y, v1.z, v1.w};
        ushort hh[8], hl[8];
#pragma unroll
        for (int j = 0; j < 8; j++) {
            __half h = __float2half_rn(vv[j]);
            hh[j] = __half_as_ushort(h);
            hl[j] = __half_as_ushort(__float2half_rn(vv[j] - __half2float(h)));
        }
        uint32_t off = boff(r, q);
        *(uint4*)(sm + OFF_U + off)        = *(uint4*)hh;   // XH (4KB)
        *(uint4*)(sm + OFF_U + 4096 + off) = *(uint4*)hl;   // XL (4KB)
    }
#pragma unroll
    for (int s = 0; s < 8; s++) {
        int i = tid + s * 256;          // 2048 = 2 splits x 256 rows x 4 groups
        int split = i >> 10, ii = i & 1023;
        int n = ii >> 2, g = ii & 3;
        const __half* src = split ? g_W1l : g_W1h;
        uint4 v = *(const uint4*)(src + n * 32 + g * 8);
        *(uint4*)(sm + OFF_U + 8192 + split * 16384 + boff(n, g)) = v;
    }
    __syncthreads();

    // ---- phase-1 mma: H = relu(X @ W1 + b1), 3-term, warp tile m32 x n64 ----
    float acc1[2][8][4];
#pragma unroll
    for (int i = 0; i < 2; i++)
#pragma unroll
        for (int j = 0; j < 8; j++)
#pragma unroll
            for (int c = 0; c < 4; c++) acc1[i][j][c] = 0.f;

#pragma unroll
    for (int t = 0; t < 2; t++) {
        uint32_t aH[2][4], aL[2][4], bb[8][2];
#pragma unroll
        for (int i = 0; i < 2; i++) {
            int r = wm * 32 + i * 16 + (lane & 15);
            int g = 2 * t + (lane >> 4);
            ldsm4(aH[i], sb + OFF_U + boff(r, g));          // XH
            ldsm4(aL[i], sb + OFF_U + 4096 + boff(r, g));   // XL
        }
#pragma unroll
        for (int p = 0; p < 4; p++) {
            int jj = wn * 8 + ((lane < 16) ? 2 * p : 2 * p + 1);
            int n = jj * 8 + (lane & 7);
            int g = 2 * t + ((lane >> 3) & 1);
            uint32_t r4[4];
            ldsm4(r4, sb + OFF_U + 8192 + boff(n, g));      // W1H
            bb[2 * p][0] = r4[0]; bb[2 * p][1] = r4[1];
            bb[2 * p + 1][0] = r4[2]; bb[2 * p + 1][1] = r4[3];
        }
#pragma unroll
        for (int i = 0; i < 2; i++)
#pragma unroll
            for (int j = 0; j < 8; j++) {
                mma16816(acc1[i][j], aH[i], bb[j]);
                mma16816(acc1[i][j], aL[i], bb[j]);
            }
#pragma unroll
        for (int p = 0; p < 4; p++) {
            int jj = wn * 8 + ((lane < 16) ? 2 * p : 2 * p + 1);
            int n = jj * 8 + (lane & 7);
            int g = 2 * t + ((lane >> 3) & 1);
            uint32_t r4[4];
            ldsm4(r4, sb + OFF_U + 24576 + boff(n, g));     // W1L
            bb[2 * p][0] = r4[0]; bb[2 * p][1] = r4[1];
            bb[2 * p + 1][0] = r4[2]; bb[2 * p + 1][1] = r4[3];
        }
#pragma unroll
        for (int i = 0; i < 2; i++)
#pragma unroll
            for (int j = 0; j < 8; j++)
                mma16816(acc1[i][j], aH[i], bb[j]);
    }

    // ---- phase-1 epilogue: +b1, relu, single fp16 into A region ----
#pragma unroll
    for (int i = 0; i < 2; i++)
#pragma unroll
        for (int j = 0; j < 8; j++) {
            int col = wn * 64 + j * 8 + 2 * (lane & 3);
            float bv0 = b1s[col], bv1 = b1s[col + 1];
            int r0 = wm * 32 + i * 16 + (lane >> 2);
#pragma unroll
            for (int half = 0; half < 2; half++) {
                int r = r0 + half * 8;
                float v0 = fmaxf(acc1[i][j][2 * half] + bv0, 0.f);
                float v1 = fmaxf(acc1[i][j][2 * half + 1] + bv1, 0.f);
                uint32_t off = aoff(r, col >> 3) + (col & 7) * 2;
                *(uint32_t*)(sm + OFF_AH + off) = packh2(v0, v1);
            }
        }
    __syncthreads();

    // ---- phase-2: single-term GEMM, B-fragments via pipelined LDG ----
    uint2 Bq[2][7];
    {
        const uint2* bb0 = g_W2p + (size_t)wn * 512 + lane;   // nt = 0
#pragma unroll
        for (int t = 0; t < 7; t++)
            if (wn == 0 || t < 6) Bq[0][t] = bb0[t * 2048];
    }

    for (int nt = 0; nt < 4; nt++) {
        float acc[2][7][4];
#pragma unroll
        for (int i = 0; i < 2; i++)
#pragma unroll
            for (int t = 0; t < 7; t++)
#pragma unroll
                for (int c = 0; c < 4; c++) acc[i][t][c] = 0.f;

        const uint2* bbase = g_W2p + (size_t)(nt * 25 + wn) * 512 + lane;

#pragma unroll
        for (int q = 0; q < 16; q++) {
            const int cur = q & 1, nxt = cur ^ 1;
            if (q < 15) {
#pragma unroll
                for (int t = 0; t < 7; t++)
                    if (wn == 0 || t < 6) Bq[nxt][t] = bbase[t * 2048 + (q + 1) * 32];
            }
            uint32_t aH[2][4];
#pragma unroll
            for (int i = 0; i < 2; i++) {
                int r = wm * 32 + i * 16 + (lane & 15);
                int g = 2 * q + (lane >> 4);
                ldsm4(aH[i], sb + OFF_AH + aoff(r, g));
            }
#pragma unroll
            for (int t = 0; t < 7; t++)
                if (t < 6 || wn == 0) {
                    const uint32_t* bp = (const uint32_t*)&Bq[cur][t];
                    mma16816(acc[0][t], aH[0], bp);
                    mma16816(acc[1][t], aH[1], bp);
                }
        }

        // protect stage: previous nt's spline readers must be done (skip nt=0)
        if (nt) __syncthreads();

        // ---- stage all 64 rows (R15 layout: row stride 204, coalesced f2) ----
#pragma unroll
        for (int i = 0; i < 2; i++)
#pragma unroll
            for (int t = 0; t < 7; t++)
                if (t < 6 || wn == 0) {
                    int col = (wn + 4 * t) * 8 + 2 * (lane & 3);
                    int r0 = wm * 32 + i * 16 + (lane >> 2);
                    *(float2*)&stage[r0 * SSTR + col] =
                        make_float2(acc[i][t][0], acc[i][t][1]);
                    *(float2*)&stage[(r0 + 8) * SSTR + col] =
                        make_float2(acc[i][t][2], acc[i][t][3]);
                }
        __syncthreads();

        // ---- preload next nt's first B-fragments (LDG hides behind spline) ----
        if (nt < 3) {
            const uint2* bbn = g_W2p + (size_t)((nt + 1) * 25 + wn) * 512 + lane;
#pragma unroll
            for (int t = 0; t < 7; t++)
                if (wn == 0 || t < 6) Bq[0][t] = bbn[t * 2048];
        }

        // ---- spline: 64 rows x 8 channels, 2 channels per thread ----
        {
            const int rl = tid >> 2;            // 0..63
            const int grow = rbase + rl;
            const float* xrow = X + (size_t)grow * D_IN + 32;
            float ladsum = 0.f;
#pragma unroll
            for (int qq = 0; qq < 2; qq++) {
                const int lc = (tid & 3) + qq * 4;   // 0..7
                const int ch = nt * 8 + lc;
                const float* sp = &stage[rl * SSTR + lc * 25];
                const float4* bp4 = (const float4*)&b2p[ch * 28];
                // bias via 7 x LDS.128 (padded table), stage via scalar (R15)
                float bb2[28];
#pragma unroll
                for (int j = 0; j < 7; j++) {
                    float4 bv = bp4[j];
                    bb2[4 * j + 0] = bv.x; bb2[4 * j + 1] = bv.y;
                    bb2[4 * j + 2] = bv.z; bb2[4 * j + 3] = bv.w;
                }
                float pr[25];
#pragma unroll
                for (int j = 0; j < 25; j++) pr[j] = sp[j] + bb2[j];

                // widths: affine softmax; Σw == 1 analytically -> no renorm
                float mw = pr[0];
#pragma unroll
                for (int j = 1; j < 8; j++) mw = fmaxf(mw, pr[j]);
                float ew[8], sw = 0.f;
#pragma unroll
                for (int j = 0; j < 8; j++) { ew[j] = __expf(pr[j] - mw); sw += ew[j]; }
                float invw = __fdividef(1.f - MINW * 8.f, sw);
                float w[8], cw[9]; cw[0] = 0.f;
#pragma unroll
                for (int j = 0; j < 8; j++) {
                    w[j] = MINW + ew[j] * invw;
                    cw[j + 1] = cw[j] + w[j];
                }

                // heights: same
                float mhh = pr[8];
#pragma unroll
                for (int j = 1; j < 8; j++) mhh = fmaxf(mhh, pr[8 + j]);
                float eh[8], sh = 0.f;
#pragma unroll
                for (int j = 0; j < 8; j++) { eh[j] = __expf(pr[8 + j] - mhh); sh += eh[j]; }
                float invh = __fdividef(1.f - MINW * 8.f, sh);
                float hh[8], chh[9]; chh[0] = 0.f;
#pragma unroll
                for (int j = 0; j < 8; j++) {
                    hh[j] = MINW + eh[j] * invh;
                    chh[j + 1] = chh[j] + hh[j];
                }

                const float x = xrow[ch];
                const bool inside = (x >= -10.f) && (x <= 10.f);
                float xs = fminf(fmaxf((x + 10.f) * 0.05f, 0.f), 1.f);

                // bin selection first (raw u values selected too)
                float xk = cw[0], wk = w[0], yk = chh[0], hk = hh[0];
                float u0 = pr[16], u1 = pr[17];
#pragma unroll
                for (int i = 1; i < 8; i++) {
                    if (xs >= cw[i]) {
                        xk = cw[i]; wk = w[i]; yk = chh[i]; hk = hh[i];
                        u0 = pr[16 + i]; u1 = pr[17 + i];
                    }
                }
                // lazy softplus on the two selected knots
                float dk  = MIND + fmaxf(u0, 0.f) + __logf(1.f + __expf(-fabsf(u0)));
                float dk1 = MIND + fmaxf(u1, 0.f) + __logf(1.f + __expf(-fabsf(u1)));

                float invwk = __fdividef(1.f, wk + EPSC);     // shared rcp
                float t   = fminf(fmaxf((xs - xk) * invwk, 0.f), 1.f);
                float a   = (hk + EPSC) * invwk;
                float omt = 1.f - t;
                float num = a * t * t + dk * t * omt;
                float den = a + (dk + dk1 - 2.f * a) * t * omt;
                float s   = __fdividef(num, den + EPSC);
                float y   = (yk + hk * s) * 20.f - 10.f;
                float dnum = a * a * (dk1 * t * t + 2.f * a * t * omt + dk * omt * omt);
                float dydx = __fdividef(dnum, den * den + EPSC);
                float ladv = __logf(fmaxf(dydx, 1e-12f));

                out[(size_t)grow * D_IN + 32 + ch] = inside ? y : x;
                ladsum += inside ? ladv : 0.f;
            }
            // reduce 4 lanes (8 channels) per row
            ladsum += __shfl_xor_sync(0xffffffffu, ladsum, 1);
            ladsum += __shfl_xor_sync(0xffffffffu, ladsum, 2);
            if ((lane & 3) == 0) lad[rl] += ladsum;
        }
    }

    __syncthreads();
    if (tid < 64) out[(size_t)B * D_IN + rbase + tid] = lad[tid];
}

// ---------------------------------------------------------------------------
extern "C" void kernel_launch(void* const* d_in, const int* in_sizes, int n_in,
                              void* d_out, int out_size)
{
    const float* X  = (const float*)d_in[0];
    const float* W1 = (const float*)d_in[1];
    const float* b1 = (const float*)d_in[2];
    const float* W2 = (const float*)d_in[3];
    const float* b2 = (const float*)d_in[4];
    float* out = (float*)d_out;

    const int B = in_sizes[0] / D_IN;

    cudaFuncSetAttribute(kmain, cudaFuncAttributeMaxDynamicSharedMemorySize, SMEM_TOT);

    kprep<<<232, 256>>>(W1, W2);
    kmain<<<B / 64, 256, SMEM_TOT>>>(X, b1, b2, out, B);
}